// round 6
// baseline (speedup 1.0000x reference)
#include <cuda_runtime.h>
#include <math.h>

#define Bc 4
#define Tt 288
#define Vv 512
#define Cc 32

// scratch (static __device__ arrays: allowed, no runtime allocation)
__device__ float g_comb[Bc * Cc * Tt * Vv];   // 75.5 MB
__device__ float g_cv[Bc * Tt * Vv];          // 2.36 MB
__device__ float g_imp[Bc * Tt];
__device__ float g_coef[Bc * 5];

// packed fp32x2 FMA (Blackwell FFMA2 — only reachable via PTX)
#define FMA2(acc, a, b) \
    asm("fma.rn.f32x2 %0, %1, %2, %0;" : "+l"(acc) : "l"(a), "l"(b))

__device__ __forceinline__ float2 upk(unsigned long long v) {
    float2 r;
    asm("mov.b64 {%0,%1}, %2;" : "=f"(r.x), "=f"(r.y) : "l"(v));
    return r;
}

// ---------------------------------------------------------------------------
// K0: impact scan + event MLP -> coefs (warp0 scans, warp1 MLP). Validated.
// ---------------------------------------------------------------------------
__global__ void k0_small(const float* __restrict__ events,
                         const float* __restrict__ ef,
                         const float* __restrict__ w1,
                         const float* __restrict__ b1,
                         const float* __restrict__ w2,
                         const float* __restrict__ b2) {
    __shared__ float sev[Bc * Tt * 3];
    __shared__ float part[12 * Tt];
    int tid = threadIdx.x;

    for (int i = tid; i < Bc * Tt * 3; i += blockDim.x) sev[i] = events[i];
    __syncthreads();

    if (tid < 12) {
        int b = tid / 3, e = tid % 3;
        const float decay[3] = {300.f, 600.f, 180.f};
        const float alpha[3] = {0.3f, 0.5f, 0.2f};
        float r = expf(-1.f / decay[e]);
        float a = alpha[e];
        float s = 0.f;
        for (int t = Tt - 1; t >= 0; --t) {
            s = sev[(b * Tt + t) * 3 + e] + r * s;
            part[tid * Tt + t] = a * s;
        }
    }

    if (tid >= 32 && tid < 32 + Bc) {
        int b = tid - 32;
        float h[32];
#pragma unroll
        for (int j = 0; j < 32; ++j) {
            float acc = b1[j];
#pragma unroll
            for (int i = 0; i < 8; ++i) acc += ef[b * 8 + i] * w1[i * 32 + j];
            h[j] = fmaxf(acc, 0.f);
        }
        float lg[5];
#pragma unroll
        for (int k = 0; k < 5; ++k) {
            float acc = b2[k];
#pragma unroll
            for (int j = 0; j < 32; ++j) acc += h[j] * w2[j * 5 + k];
            lg[k] = 1.f / (1.f + expf(-acc));
        }
        float m = lg[0];
#pragma unroll
        for (int k = 1; k < 5; ++k) m = fmaxf(m, lg[k]);
        float ex[5];
        float ssum = 0.f;
#pragma unroll
        for (int k = 0; k < 5; ++k) { ex[k] = expf(lg[k] - m); ssum += ex[k]; }
        const float ks[5] = {3.f, 6.f, 12.f, 24.f, 48.f};
#pragma unroll
        for (int k = 0; k < 5; ++k) g_coef[b * 5 + k] = ex[k] / (ssum * ks[k]);
    }
    __syncthreads();
    for (int i = tid; i < Bc * Tt; i += blockDim.x) {
        int b = i / Tt, t = i - b * Tt;
        g_imp[i] = part[(b * 3 + 0) * Tt + t] +
                   part[(b * 3 + 1) * Tt + t] +
                   part[(b * 3 + 2) * Tt + t];
    }
}

// ---------------------------------------------------------------------------
// Kcv: rolling mean / Bessel std over W=60 (unchanged, validated).
// ---------------------------------------------------------------------------
__global__ void __launch_bounds__(256) k_cv(const float* __restrict__ flow) {
    __shared__ float sf[Tt * 32];
    int tid = threadIdx.x;
    int v0 = blockIdx.x * 32;
    int b = blockIdx.y;

    for (int i = tid; i < Tt * 32; i += 256) {
        int t = i >> 5, v = i & 31;
        sf[i] = flow[(size_t)(b * Tt + t) * Vv + v0 + v];
    }
    __syncthreads();

    int v = tid & 31;
    int ch = tid >> 5;
    int ts = ch * 36;

    float s = 0.f, s2 = 0.f;
    int j0 = ts - 60; if (j0 < 0) j0 = 0;
    for (int j = j0; j < ts; ++j) {
        float f = sf[j * 32 + v];
        s += f; s2 += f * f;
    }
    float* cp = g_cv + (size_t)b * Tt * Vv + v0 + v;
#pragma unroll 4
    for (int t = ts; t < ts + 36; ++t) {
        float f = sf[t * 32 + v];
        s += f; s2 += f * f;
        if (t >= 60) {
            float fo = sf[(t - 60) * 32 + v];
            s -= fo; s2 -= fo * fo;
        }
        float c = 0.f;
        if (t >= 59) {
            float mean = s * (1.f / 60.f);
            float var = (s2 - 60.f * mean * mean) * (1.f / 59.f);
            var = fmaxf(var, 0.f);
            c = sqrtf(var) / (mean + 1e-6f);
        }
        cp[(size_t)t * Vv] = c;
    }
}

// ---------------------------------------------------------------------------
// K1 v2: expert filter, float2 columns + depth-8 LDG prefetch pipeline.
// Per thread: one (b,c,v-pair) column; 64-deep float2 ring in dynamic smem,
// column == tid (private, no barriers). Same validated window recurrence as
// round 3, re-indexed by tin = t+23:
//   adds:  z[tin-22], z[tin-21], z[tin-18], z[tin-12], z[tin]
//   drops: z[tin-25], z[tin-27], z[tin-30], z[tin-36], z[tin-48]
// ---------------------------------------------------------------------------
__global__ void __launch_bounds__(128) k1_filter2(const float* __restrict__ xf) {
    extern __shared__ float2 rb2[];       // [64][128] = 64 KB
    const float2* x2 = reinterpret_cast<const float2*>(xf);
    int tid = threadIdx.x;
    int idx = blockIdx.x * 128 + tid;     // 0 .. 32767
    int vp = idx & 255;
    int bc = idx >> 8;
    int b  = bc >> 5;
    const float2* xp = x2 + (size_t)bc * Tt * 256 + vp;
    float2*       cp = reinterpret_cast<float2*>(g_comb) + (size_t)bc * Tt * 256 + vp;

    float c0 = g_coef[b * 5 + 0];
    float c1 = g_coef[b * 5 + 1];
    float c2 = g_coef[b * 5 + 2];
    float c3 = g_coef[b * 5 + 3];
    float c4 = g_coef[b * 5 + 4];

#pragma unroll
    for (int s = 0; s < 64; ++s) rb2[s * 128 + tid] = make_float2(0.f, 0.f);

    float2 S0 = make_float2(0.f, 0.f), S1 = S0, S2 = S0, S3 = S0, S4 = S0;

    float2 f[8];
#pragma unroll
    for (int j = 0; j < 8; ++j) {
        int t0 = j - 1;                                   // tin = -1..6
        f[j] = (t0 >= 0) ? __ldg(xp + (size_t)t0 * 256) : make_float2(0.f, 0.f);
    }

    int tin = -1;
    for (int g = 0; g < 39; ++g) {                        // 39*8 = 312 steps
#pragma unroll
        for (int j = 0; j < 8; ++j) {
            float2 xin = f[j];
            float2 a3  = rb2[((tin - 22) & 63) * 128 + tid];
            float2 a6  = rb2[((tin - 21) & 63) * 128 + tid];
            float2 a12 = rb2[((tin - 18) & 63) * 128 + tid];
            float2 a24 = rb2[((tin - 12) & 63) * 128 + tid];
            float2 d3  = rb2[((tin - 25) & 63) * 128 + tid];
            float2 d6  = rb2[((tin - 27) & 63) * 128 + tid];
            float2 d12 = rb2[((tin - 30) & 63) * 128 + tid];
            float2 d24 = rb2[((tin - 36) & 63) * 128 + tid];
            float2 d48 = rb2[((tin - 48) & 63) * 128 + tid];

            S0.x += a3.x  - d3.x;   S0.y += a3.y  - d3.y;
            S1.x += a6.x  - d6.x;   S1.y += a6.y  - d6.y;
            S2.x += a12.x - d12.x;  S2.y += a12.y - d12.y;
            S3.x += a24.x - d24.x;  S3.y += a24.y - d24.y;
            S4.x += xin.x - d48.x;  S4.y += xin.y - d48.y;

            rb2[(tin & 63) * 128 + tid] = xin;

            if (tin >= 23) {
                float2 o;
                o.x = c0 * S0.x + c1 * S1.x + c2 * S2.x + c3 * S3.x + c4 * S4.x;
                o.y = c0 * S0.y + c1 * S1.y + c2 * S2.y + c3 * S3.y + c4 * S4.y;
                cp[(size_t)(tin - 23) * 256] = o;
            }
            int tn = tin + 8;
            f[j] = (tn < Tt) ? __ldg(xp + (size_t)tn * 256) : make_float2(0.f, 0.f);
            ++tin;
        }
    }
}

// ---------------------------------------------------------------------------
// K2 v3: fused channel mix + residual + CV + impact. FFMA2, wavefront-minimal.
// Block: (b, t, 256-v tile), 256 threads. Thread tile 8o x 4p (2 f32x2 pairs).
// og = tid&3 (o = og*8..+7), pg = tid>>2 (p = pg*4..+3).
// Per c per warp: 1 cat LDS.128 (8 distinct 16B, 4-way bcast = 1 wavefront)
//              + 4 dup-weight LDS.128 (4 distinct 16B, 8-way bcast = 1 wf ea)
// => 5 wavefronts per 64 FMA lanes. acc = 16 u64 = 32 regs.
// ---------------------------------------------------------------------------
__global__ void __launch_bounds__(256, 2) k2_mix3(const float* __restrict__ x,
                                                  const float* __restrict__ fw,
                                                  const float* __restrict__ fb,
                                                  float* __restrict__ out) {
    extern __shared__ __align__(16) float smem[];
    float*  s_cat = smem;                               // [64][256]  64 KB
    float2* s_wd  = reinterpret_cast<float2*>(smem + 64 * 256);  // [64][32] 16 KB
    float*  cvs   = reinterpret_cast<float*>(s_wd + 64 * 32);    // [256]  1 KB

    int tid = threadIdx.x;
    int v0 = blockIdx.x * 256;
    int t0 = blockIdx.y;
    int b  = blockIdx.z;

    // cat tile: rows 0..31 = x, rows 32..63 = comb (float4, coalesced)
    const float4* x4 = reinterpret_cast<const float4*>(x);
    const float4* m4 = reinterpret_cast<const float4*>(g_comb);
    float4* cat4 = reinterpret_cast<float4*>(s_cat);
#pragma unroll
    for (int k = 0; k < 16; ++k) {
        int i = tid + k * 256;            // 0..4095
        int c = i >> 6, q = i & 63;
        int gi = ((b * Cc + (c & 31)) * Tt + t0) * (Vv / 4) + (v0 >> 2) + q;
        cat4[c * 64 + q] = (c < 32) ? x4[gi] : m4[gi];
    }
    // duplicated weights: s_wd[c][o] = (w[o][c], w[o][c])
#pragma unroll
    for (int k = 0; k < 8; ++k) {
        int i = tid + k * 256;            // 0..2047
        int o = i >> 6, c = i & 63;
        float w = fw[o * 64 + c];
        s_wd[c * 32 + o] = make_float2(w, w);
    }
    cvs[tid] = g_cv[(size_t)(b * Tt + t0) * Vv + v0 + tid];
    __syncthreads();

    int og = tid & 3;                     // o = og*8 .. og*8+7
    int pg = tid >> 2;                    // p = pg*4 .. pg*4+3
    int p0 = pg << 2;

    unsigned long long acc[8][2];
#pragma unroll
    for (int oo = 0; oo < 8; ++oo) { acc[oo][0] = 0ull; acc[oo][1] = 0ull; }

#pragma unroll 4
    for (int c = 0; c < 64; ++c) {
        ulonglong2 xv =
            *reinterpret_cast<const ulonglong2*>(&s_cat[c * 256 + p0]);
        const ulonglong2* wr =
            reinterpret_cast<const ulonglong2*>(&s_wd[c * 32 + og * 8]);
        ulonglong2 w01 = wr[0];
        ulonglong2 w23 = wr[1];
        ulonglong2 w45 = wr[2];
        ulonglong2 w67 = wr[3];
        FMA2(acc[0][0], w01.x, xv.x); FMA2(acc[0][1], w01.x, xv.y);
        FMA2(acc[1][0], w01.y, xv.x); FMA2(acc[1][1], w01.y, xv.y);
        FMA2(acc[2][0], w23.x, xv.x); FMA2(acc[2][1], w23.x, xv.y);
        FMA2(acc[3][0], w23.y, xv.x); FMA2(acc[3][1], w23.y, xv.y);
        FMA2(acc[4][0], w45.x, xv.x); FMA2(acc[4][1], w45.x, xv.y);
        FMA2(acc[5][0], w45.y, xv.x); FMA2(acc[5][1], w45.y, xv.y);
        FMA2(acc[6][0], w67.x, xv.x); FMA2(acc[6][1], w67.x, xv.y);
        FMA2(acc[7][0], w67.y, xv.x); FMA2(acc[7][1], w67.y, xv.y);
    }

    // epilogue: (gemm + bias + residual) * (1+cv) + impact
    float m0 = 1.f + cvs[p0 + 0];
    float m1 = 1.f + cvs[p0 + 1];
    float m2 = 1.f + cvs[p0 + 2];
    float m3 = 1.f + cvs[p0 + 3];
    float imp = __ldg(g_imp + b * Tt + t0);

#pragma unroll
    for (int oo = 0; oo < 8; ++oo) {
        int o = (og << 3) + oo;
        float2 lo = upk(acc[oo][0]);
        float2 hi = upk(acc[oo][1]);
        float fbv = __ldg(fb + o);
        float4 xres = *reinterpret_cast<const float4*>(&s_cat[o * 256 + p0]);
        float4 r;
        r.x = (lo.x + fbv + xres.x) * m0 + imp;
        r.y = (lo.y + fbv + xres.y) * m1 + imp;
        r.z = (hi.x + fbv + xres.z) * m2 + imp;
        r.w = (hi.y + fbv + xres.w) * m3 + imp;
        size_t oi = ((size_t)(b * Cc + o) * Tt + t0) * Vv + v0 + p0;
        *reinterpret_cast<float4*>(out + oi) = r;
    }
}

// ---------------------------------------------------------------------------
extern "C" void kernel_launch(void* const* d_in, const int* in_sizes, int n_in,
                              void* d_out, int out_size) {
    const float* flow   = (const float*)d_in[0];
    const float* events = (const float*)d_in[1];
    const float* x      = (const float*)d_in[2];
    const float* ef     = (const float*)d_in[3];
    const float* w1     = (const float*)d_in[4];
    const float* b1     = (const float*)d_in[5];
    const float* w2     = (const float*)d_in[6];
    const float* b2     = (const float*)d_in[7];
    const float* fw     = (const float*)d_in[8];
    const float* fb     = (const float*)d_in[9];
    float* out = (float*)d_out;

    const int smem_k1 = 64 * 128 * sizeof(float2);                 // 64 KB
    const int smem_k2 = 64 * 256 * 4 + 64 * 32 * 8 + 256 * 4;      // ~81 KB
    static bool attr_done = false;
    if (!attr_done) {
        cudaFuncSetAttribute(k1_filter2,
            cudaFuncAttributeMaxDynamicSharedMemorySize, smem_k1);
        cudaFuncSetAttribute(k2_mix3,
            cudaFuncAttributeMaxDynamicSharedMemorySize, smem_k2);
        attr_done = true;
    }

    k0_small<<<1, 128>>>(events, ef, w1, b1, w2, b2);
    k_cv<<<dim3(Vv / 32, Bc), 256>>>(flow);
    k1_filter2<<<(Bc * Cc * (Vv / 2)) / 128, 128, smem_k1>>>(x);
    k2_mix3<<<dim3(Vv / 256, Tt, Bc), 256, smem_k2>>>(x, fw, fb, out);
}

// round 7
// speedup vs baseline: 1.1409x; 1.1409x over previous
#include <cuda_runtime.h>
#include <math.h>

#define Bc 4
#define Tt 288
#define Vv 512
#define Cc 32

// scratch (static __device__ arrays: allowed, no runtime allocation)
__device__ float g_comb[Bc * Cc * Tt * Vv];   // 75.5 MB
__device__ float g_cv[Bc * Tt * Vv];          // 2.36 MB
__device__ float g_imp[Bc * Tt];
__device__ float g_coef[Bc * 5];

// packed fp32x2 FMA (Blackwell FFMA2 — only reachable via PTX)
#define FMA2(acc, a, b) \
    asm("fma.rn.f32x2 %0, %1, %2, %0;" : "+l"(acc) : "l"(a), "l"(b))

__device__ __forceinline__ float2 upk(unsigned long long v) {
    float2 r;
    asm("mov.b64 {%0,%1}, %2;" : "=f"(r.x), "=f"(r.y) : "l"(v));
    return r;
}

// ---------------------------------------------------------------------------
// K0: impact scan + event MLP -> coefs (warp0 scans, warp1 MLP). Validated.
// ---------------------------------------------------------------------------
__global__ void k0_small(const float* __restrict__ events,
                         const float* __restrict__ ef,
                         const float* __restrict__ w1,
                         const float* __restrict__ b1,
                         const float* __restrict__ w2,
                         const float* __restrict__ b2) {
    __shared__ float sev[Bc * Tt * 3];
    __shared__ float part[12 * Tt];
    int tid = threadIdx.x;

    for (int i = tid; i < Bc * Tt * 3; i += blockDim.x) sev[i] = events[i];
    __syncthreads();

    if (tid < 12) {
        int b = tid / 3, e = tid % 3;
        const float decay[3] = {300.f, 600.f, 180.f};
        const float alpha[3] = {0.3f, 0.5f, 0.2f};
        float r = expf(-1.f / decay[e]);
        float a = alpha[e];
        float s = 0.f;
        for (int t = Tt - 1; t >= 0; --t) {
            s = sev[(b * Tt + t) * 3 + e] + r * s;
            part[tid * Tt + t] = a * s;
        }
    }

    if (tid >= 32 && tid < 32 + Bc) {
        int b = tid - 32;
        float h[32];
#pragma unroll
        for (int j = 0; j < 32; ++j) {
            float acc = b1[j];
#pragma unroll
            for (int i = 0; i < 8; ++i) acc += ef[b * 8 + i] * w1[i * 32 + j];
            h[j] = fmaxf(acc, 0.f);
        }
        float lg[5];
#pragma unroll
        for (int k = 0; k < 5; ++k) {
            float acc = b2[k];
#pragma unroll
            for (int j = 0; j < 32; ++j) acc += h[j] * w2[j * 5 + k];
            lg[k] = 1.f / (1.f + expf(-acc));
        }
        float m = lg[0];
#pragma unroll
        for (int k = 1; k < 5; ++k) m = fmaxf(m, lg[k]);
        float ex[5];
        float ssum = 0.f;
#pragma unroll
        for (int k = 0; k < 5; ++k) { ex[k] = expf(lg[k] - m); ssum += ex[k]; }
        const float ks[5] = {3.f, 6.f, 12.f, 24.f, 48.f};
#pragma unroll
        for (int k = 0; k < 5; ++k) g_coef[b * 5 + k] = ex[k] / (ssum * ks[k]);
    }
    __syncthreads();
    for (int i = tid; i < Bc * Tt; i += blockDim.x) {
        int b = i / Tt, t = i - b * Tt;
        g_imp[i] = part[(b * 3 + 0) * Tt + t] +
                   part[(b * 3 + 1) * Tt + t] +
                   part[(b * 3 + 2) * Tt + t];
    }
}

// ---------------------------------------------------------------------------
// Kcv: rolling mean / Bessel std over W=60 (unchanged, validated).
// ---------------------------------------------------------------------------
__global__ void __launch_bounds__(256) k_cv(const float* __restrict__ flow) {
    __shared__ float sf[Tt * 32];
    int tid = threadIdx.x;
    int v0 = blockIdx.x * 32;
    int b = blockIdx.y;

    for (int i = tid; i < Tt * 32; i += 256) {
        int t = i >> 5, v = i & 31;
        sf[i] = flow[(size_t)(b * Tt + t) * Vv + v0 + v];
    }
    __syncthreads();

    int v = tid & 31;
    int ch = tid >> 5;
    int ts = ch * 36;

    float s = 0.f, s2 = 0.f;
    int j0 = ts - 60; if (j0 < 0) j0 = 0;
    for (int j = j0; j < ts; ++j) {
        float f = sf[j * 32 + v];
        s += f; s2 += f * f;
    }
    float* cp = g_cv + (size_t)b * Tt * Vv + v0 + v;
#pragma unroll 4
    for (int t = ts; t < ts + 36; ++t) {
        float f = sf[t * 32 + v];
        s += f; s2 += f * f;
        if (t >= 60) {
            float fo = sf[(t - 60) * 32 + v];
            s -= fo; s2 -= fo * fo;
        }
        float c = 0.f;
        if (t >= 59) {
            float mean = s * (1.f / 60.f);
            float var = (s2 - 60.f * mean * mean) * (1.f / 59.f);
            var = fmaxf(var, 0.f);
            c = sqrtf(var) / (mean + 1e-6f);
        }
        cp[(size_t)t * Vv] = c;
    }
}

// ---------------------------------------------------------------------------
// K1 (t-split x2): event-weighted expert filter, same validated recurrence as
// round 3, but each block computes half the t-range. Warm-up from a zeroed
// ring starting 72 iterations before the first output: the deepest ring read
// at output t is x[t-25], written at iteration t-48 >= start, and all window
// sums telescope to exact values after 48 add-steps (drops read zeros before
// that, matching empty-state). For ts=0 this reduces to the original scan.
// ---------------------------------------------------------------------------
#define SL(i) ((((i) + 128) & 63) * 128 + tid)

__global__ void __launch_bounds__(128) k1_filter(const float* __restrict__ x) {
    __shared__ float rb[64 * 128];
    int tid = threadIdx.x;
    int col = blockIdx.x * 128 + tid;
    int half = blockIdx.y;                  // 0 or 1
    int ts = half * (Tt / 2);
    int te = ts + (Tt / 2);
    int v = col & (Vv - 1);
    int bc = col >> 9;
    int b = bc >> 5;
    const float* xp = x + (size_t)bc * Tt * Vv + v;
    float* cp = g_comb + (size_t)bc * Tt * Vv + v;

    float c0 = g_coef[b * 5 + 0];
    float c1 = g_coef[b * 5 + 1];
    float c2 = g_coef[b * 5 + 2];
    float c3 = g_coef[b * 5 + 3];
    float c4 = g_coef[b * 5 + 4];

#pragma unroll
    for (int s = 0; s < 64; ++s) rb[s * 128 + tid] = 0.f;

    float S0 = 0.f, S1 = 0.f, S2 = 0.f, S3 = 0.f, S4 = 0.f;

#pragma unroll 4
    for (int t = ts - 72; t < te; ++t) {
        float a3  = rb[SL(t + 1)];
        float a6  = rb[SL(t + 2)];
        float a12 = rb[SL(t + 5)];
        float a24 = rb[SL(t + 11)];
        float d3  = rb[SL(t - 2)];
        float d6  = rb[SL(t - 4)];
        float d12 = rb[SL(t - 7)];
        float d24 = rb[SL(t - 13)];
        float d48 = rb[SL(t - 25)];

        int tin = t + 23;
        float xin = 0.f;
        if ((unsigned)tin < (unsigned)Tt) xin = __ldg(xp + (size_t)tin * Vv);

        S0 += a3  - d3;
        S1 += a6  - d6;
        S2 += a12 - d12;
        S3 += a24 - d24;
        S4 += xin - d48;

        rb[SL(tin)] = xin;

        if (t >= ts) {
            cp[(size_t)t * Vv] =
                c0 * S0 + c1 * S1 + c2 * S2 + c3 * S3 + c4 * S4;
        }
    }
}

// ---------------------------------------------------------------------------
// K2 v4: fused channel mix + residual + CV + impact. FFMA2, LOW-REGISTER.
// Block: (b, t, 128-v tile), 256 threads = 8 warps. Thread tile 4o x 4p:
//   og = warp id (0..7) -> o = og*4..og*4+3 (weight LDS fully broadcast)
//   pg = lane (0..31)   -> p = pg*4..pg*4+3
// Per c per thread: 1 cat LDS.128 + 2 dup-weight LDS.128 (bcast) + 8 FFMA2.
// acc = 8 u64 = 16 regs -> ~50 regs total, 48KB static smem -> 4 blocks/SM.
// ---------------------------------------------------------------------------
__global__ void __launch_bounds__(256) k2_mix4(const float* __restrict__ x,
                                               const float* __restrict__ fw,
                                               const float* __restrict__ fb,
                                               float* __restrict__ out) {
    __shared__ __align__(16) float  s_cat[64 * 128];   // 32 KB  [c][p]
    __shared__ __align__(16) float2 s_wd[64 * 32];     // 16 KB  [c][o] dup pairs

    int tid = threadIdx.x;
    int v0 = blockIdx.x * 128;
    int t0 = blockIdx.y;
    int b  = blockIdx.z;

    // cat tile: rows 0..31 = x, rows 32..63 = comb (float4, coalesced)
    const float4* x4 = reinterpret_cast<const float4*>(x);
    const float4* m4 = reinterpret_cast<const float4*>(g_comb);
    float4* cat4 = reinterpret_cast<float4*>(s_cat);
#pragma unroll
    for (int k = 0; k < 8; ++k) {
        int i = tid + k * 256;            // 0..2047
        int c = i >> 5, r = i & 31;
        int gi = ((b * Cc + (c & 31)) * Tt + t0) * (Vv / 4) + (v0 >> 2) + r;
        cat4[c * 32 + r] = (c < 32) ? x4[gi] : m4[gi];
    }
    // duplicated weights: s_wd[c][o] = (w[o][c], w[o][c])
#pragma unroll
    for (int k = 0; k < 8; ++k) {
        int i = tid + k * 256;            // 0..2047
        int o = i & 31, c = i >> 5;
        float w = fw[o * 64 + c];
        s_wd[c * 32 + o] = make_float2(w, w);
    }
    __syncthreads();

    int og = tid >> 5;                    // warp id: o = og*4 .. og*4+3
    int pg = tid & 31;                    // lane:    p = pg*4 .. pg*4+3
    int p0 = pg << 2;

    unsigned long long acc[4][2];
#pragma unroll
    for (int oo = 0; oo < 4; ++oo) { acc[oo][0] = 0ull; acc[oo][1] = 0ull; }

#pragma unroll 4
    for (int c = 0; c < 64; ++c) {
        ulonglong2 xv =
            *reinterpret_cast<const ulonglong2*>(&s_cat[c * 128 + p0]);
        const ulonglong2* wr =
            reinterpret_cast<const ulonglong2*>(&s_wd[c * 32 + (og << 2)]);
        ulonglong2 w01 = wr[0];
        ulonglong2 w23 = wr[1];
        FMA2(acc[0][0], w01.x, xv.x); FMA2(acc[0][1], w01.x, xv.y);
        FMA2(acc[1][0], w01.y, xv.x); FMA2(acc[1][1], w01.y, xv.y);
        FMA2(acc[2][0], w23.x, xv.x); FMA2(acc[2][1], w23.x, xv.y);
        FMA2(acc[3][0], w23.y, xv.x); FMA2(acc[3][1], w23.y, xv.y);
    }

    // epilogue: (gemm + bias + residual) * (1+cv) + impact
    float4 cvv = *reinterpret_cast<const float4*>(
        g_cv + (size_t)(b * Tt + t0) * Vv + v0 + p0);
    float m0 = 1.f + cvv.x, m1 = 1.f + cvv.y;
    float m2 = 1.f + cvv.z, m3 = 1.f + cvv.w;
    float imp = __ldg(g_imp + b * Tt + t0);

#pragma unroll
    for (int oo = 0; oo < 4; ++oo) {
        int o = (og << 2) + oo;
        float2 lo = upk(acc[oo][0]);
        float2 hi = upk(acc[oo][1]);
        float fbv = __ldg(fb + o);
        float4 xres = *reinterpret_cast<const float4*>(&s_cat[o * 128 + p0]);
        float4 r;
        r.x = (lo.x + fbv + xres.x) * m0 + imp;
        r.y = (lo.y + fbv + xres.y) * m1 + imp;
        r.z = (hi.x + fbv + xres.z) * m2 + imp;
        r.w = (hi.y + fbv + xres.w) * m3 + imp;
        size_t oi = ((size_t)(b * Cc + o) * Tt + t0) * Vv + v0 + p0;
        *reinterpret_cast<float4*>(out + oi) = r;
    }
}

// ---------------------------------------------------------------------------
extern "C" void kernel_launch(void* const* d_in, const int* in_sizes, int n_in,
                              void* d_out, int out_size) {
    const float* flow   = (const float*)d_in[0];
    const float* events = (const float*)d_in[1];
    const float* x      = (const float*)d_in[2];
    const float* ef     = (const float*)d_in[3];
    const float* w1     = (const float*)d_in[4];
    const float* b1     = (const float*)d_in[5];
    const float* w2     = (const float*)d_in[6];
    const float* b2     = (const float*)d_in[7];
    const float* fw     = (const float*)d_in[8];
    const float* fb     = (const float*)d_in[9];
    float* out = (float*)d_out;

    k0_small<<<1, 128>>>(events, ef, w1, b1, w2, b2);
    k_cv<<<dim3(Vv / 32, Bc), 256>>>(flow);
    k1_filter<<<dim3((Bc * Cc * Vv) / 128, 2), 128>>>(x);
    k2_mix4<<<dim3(Vv / 128, Tt, Bc), 256>>>(x, fw, fb, out);
}

// round 8
// speedup vs baseline: 1.4329x; 1.2559x over previous
#include <cuda_runtime.h>
#include <cuda_bf16.h>
#include <math.h>

#define Bc 4
#define Tt 288
#define Vv 512
#define Cc 32

// scratch (static __device__ arrays: allowed, no runtime allocation)
__device__ __nv_bfloat162 g_comb[Bc * Cc * Tt * (Vv / 2)];   // 37.7 MB
__device__ float g_cv[Bc * Tt * Vv];                          // 2.36 MB
__device__ float g_imp[Bc * Tt];
__device__ float g_coef[Bc * 5];

// ---------------------------------------------------------------------------
// kA: merged small kernels. Block 64 = impact scan + event MLP (k0);
// blocks 0..63 = rolling CV (k_cv). One launch instead of two.
// ---------------------------------------------------------------------------
__global__ void __launch_bounds__(256) kA(const float* __restrict__ flow,
                                          const float* __restrict__ events,
                                          const float* __restrict__ ef,
                                          const float* __restrict__ w1,
                                          const float* __restrict__ b1,
                                          const float* __restrict__ w2,
                                          const float* __restrict__ b2) {
    int tid = threadIdx.x;
    if (blockIdx.x == 64) {
        // ---- k0 path (validated) ----
        __shared__ float sev[Bc * Tt * 3];
        __shared__ float part[12 * Tt];
        for (int i = tid; i < Bc * Tt * 3; i += blockDim.x) sev[i] = events[i];
        __syncthreads();

        if (tid < 12) {
            int b = tid / 3, e = tid % 3;
            const float decay[3] = {300.f, 600.f, 180.f};
            const float alpha[3] = {0.3f, 0.5f, 0.2f};
            float r = expf(-1.f / decay[e]);
            float a = alpha[e];
            float s = 0.f;
            for (int t = Tt - 1; t >= 0; --t) {
                s = sev[(b * Tt + t) * 3 + e] + r * s;
                part[tid * Tt + t] = a * s;
            }
        }
        if (tid >= 32 && tid < 32 + Bc) {
            int b = tid - 32;
            float h[32];
#pragma unroll
            for (int j = 0; j < 32; ++j) {
                float acc = b1[j];
#pragma unroll
                for (int i = 0; i < 8; ++i) acc += ef[b * 8 + i] * w1[i * 32 + j];
                h[j] = fmaxf(acc, 0.f);
            }
            float lg[5];
#pragma unroll
            for (int k = 0; k < 5; ++k) {
                float acc = b2[k];
#pragma unroll
                for (int j = 0; j < 32; ++j) acc += h[j] * w2[j * 5 + k];
                lg[k] = 1.f / (1.f + expf(-acc));
            }
            float m = lg[0];
#pragma unroll
            for (int k = 1; k < 5; ++k) m = fmaxf(m, lg[k]);
            float ex[5];
            float ssum = 0.f;
#pragma unroll
            for (int k = 0; k < 5; ++k) { ex[k] = expf(lg[k] - m); ssum += ex[k]; }
            const float ks[5] = {3.f, 6.f, 12.f, 24.f, 48.f};
#pragma unroll
            for (int k = 0; k < 5; ++k) g_coef[b * 5 + k] = ex[k] / (ssum * ks[k]);
        }
        __syncthreads();
        for (int i = tid; i < Bc * Tt; i += blockDim.x) {
            int b = i / Tt, t = i - b * Tt;
            g_imp[i] = part[(b * 3 + 0) * Tt + t] +
                       part[(b * 3 + 1) * Tt + t] +
                       part[(b * 3 + 2) * Tt + t];
        }
        return;
    }

    // ---- k_cv path (validated) ----
    __shared__ float sf[Tt * 32];
    int v0 = (blockIdx.x & 15) * 32;
    int b  = blockIdx.x >> 4;

    for (int i = tid; i < Tt * 32; i += 256) {
        int t = i >> 5, v = i & 31;
        sf[i] = flow[(size_t)(b * Tt + t) * Vv + v0 + v];
    }
    __syncthreads();

    int v = tid & 31;
    int ch = tid >> 5;
    int ts = ch * 36;

    float s = 0.f, s2 = 0.f;
    int j0 = ts - 60; if (j0 < 0) j0 = 0;
    for (int j = j0; j < ts; ++j) {
        float f = sf[j * 32 + v];
        s += f; s2 += f * f;
    }
    float* cp = g_cv + (size_t)b * Tt * Vv + v0 + v;
#pragma unroll 4
    for (int t = ts; t < ts + 36; ++t) {
        float f = sf[t * 32 + v];
        s += f; s2 += f * f;
        if (t >= 60) {
            float fo = sf[(t - 60) * 32 + v];
            s -= fo; s2 -= fo * fo;
        }
        float c = 0.f;
        if (t >= 59) {
            float mean = s * (1.f / 60.f);
            float var = (s2 - 60.f * mean * mean) * (1.f / 59.f);
            var = fmaxf(var, 0.f);
            c = sqrtf(var) / (mean + 1e-6f);
        }
        cp[(size_t)t * Vv] = c;
    }
}

// ---------------------------------------------------------------------------
// K1: expert filter. float2 columns, depth-8 LDG prefetch (validated R5) +
// t-split x2 (warm-up from zeroed ring, scheme validated R7). Output bf16x2.
// Recurrence (tin coords): adds z[tin-22], z[tin-21], z[tin-18], z[tin-12],
// z[tin]; drops z[tin-25], z[tin-27], z[tin-30], z[tin-36], z[tin-48].
// Block covers 144 output t's; scan starts 72 steps earlier (49-step warm-up
// before first output at tin = ts+23) so every window add lands in-scan and
// pre-start drops read zeros -> exact telescoping.
// ---------------------------------------------------------------------------
__global__ void __launch_bounds__(128) k1f(const float* __restrict__ xf) {
    extern __shared__ float2 rb2[];       // [64][128] = 64 KB
    const float2* x2 = reinterpret_cast<const float2*>(xf);
    int tid = threadIdx.x;
    int idx = blockIdx.x * 128 + tid;     // 0 .. 32767 (b,c,vpair)
    int ts = blockIdx.y * 144;            // output range [ts, ts+144)
    int vp = idx & 255;
    int bc = idx >> 8;
    int b  = bc >> 5;
    const float2* xp = x2 + (size_t)bc * Tt * 256 + vp;
    __nv_bfloat162* cp = g_comb + (size_t)bc * Tt * 256 + vp;

    float c0 = g_coef[b * 5 + 0];
    float c1 = g_coef[b * 5 + 1];
    float c2 = g_coef[b * 5 + 2];
    float c3 = g_coef[b * 5 + 3];
    float c4 = g_coef[b * 5 + 4];

#pragma unroll
    for (int s = 0; s < 64; ++s) rb2[s * 128 + tid] = make_float2(0.f, 0.f);

    float2 S0 = make_float2(0.f, 0.f), S1 = S0, S2 = S0, S3 = S0, S4 = S0;

    float2 f[8];
#pragma unroll
    for (int j = 0; j < 8; ++j) {
        int tn = ts - 49 + j;
        f[j] = ((unsigned)tn < (unsigned)Tt)
                 ? __ldg(xp + (size_t)tn * 256) : make_float2(0.f, 0.f);
    }

    int tin = ts - 49;
    int tout0 = ts + 23;
    for (int g = 0; g < 27; ++g) {        // 27*8 = 216 steps
#pragma unroll
        for (int j = 0; j < 8; ++j) {
            float2 xin = f[j];
            float2 a3  = rb2[((tin - 22) & 63) * 128 + tid];
            float2 a6  = rb2[((tin - 21) & 63) * 128 + tid];
            float2 a12 = rb2[((tin - 18) & 63) * 128 + tid];
            float2 a24 = rb2[((tin - 12) & 63) * 128 + tid];
            float2 d3  = rb2[((tin - 25) & 63) * 128 + tid];
            float2 d6  = rb2[((tin - 27) & 63) * 128 + tid];
            float2 d12 = rb2[((tin - 30) & 63) * 128 + tid];
            float2 d24 = rb2[((tin - 36) & 63) * 128 + tid];
            float2 d48 = rb2[((tin - 48) & 63) * 128 + tid];

            S0.x += a3.x  - d3.x;   S0.y += a3.y  - d3.y;
            S1.x += a6.x  - d6.x;   S1.y += a6.y  - d6.y;
            S2.x += a12.x - d12.x;  S2.y += a12.y - d12.y;
            S3.x += a24.x - d24.x;  S3.y += a24.y - d24.y;
            S4.x += xin.x - d48.x;  S4.y += xin.y - d48.y;

            rb2[(tin & 63) * 128 + tid] = xin;

            if (tin >= tout0) {
                float ox = c0 * S0.x + c1 * S1.x + c2 * S2.x + c3 * S3.x + c4 * S4.x;
                float oy = c0 * S0.y + c1 * S1.y + c2 * S2.y + c3 * S3.y + c4 * S4.y;
                cp[(size_t)(tin - 23) * 256] = __floats2bfloat162_rn(ox, oy);
            }
            int tn = tin + 8;
            f[j] = ((unsigned)tn < (unsigned)Tt)
                     ? __ldg(xp + (size_t)tn * 256) : make_float2(0.f, 0.f);
            ++tin;
        }
    }
}

// ---------------------------------------------------------------------------
// K2 v5: fused channel mix + residual + CV + impact. PLAIN SCALAR FFMA.
// Block: (b, t, 128-v), 256 thr = 8 warps. Thread tile 4o x 4p:
//   og = warp id -> o = og*4..+3 (weight LDS.128 fully broadcast, 1 wavefront)
//   pg = lane    -> p = pg*4..+3 (cat LDS.128 distinct 512B, conflict-free)
// Per warp-c: 2 LDS + 16 FFMA (rt=2). 16 acc regs -> ~40 regs, 41KB smem.
// comb read as bf16, converted during fill.
// ---------------------------------------------------------------------------
__global__ void __launch_bounds__(256) k2s(const float* __restrict__ x,
                                           const float* __restrict__ fw,
                                           const float* __restrict__ fb,
                                           float* __restrict__ out) {
    __shared__ __align__(16) float s_cat[64 * 128];   // 32 KB [c][p]
    __shared__ __align__(16) float s_w[64 * 32];      // 8 KB  [c][o]
    __shared__ float s_cv[128];

    int tid = threadIdx.x;
    int v0 = blockIdx.x * 128;
    int t0 = blockIdx.y;
    int b  = blockIdx.z;

    // x rows 0..31 (float4)
    const float4* x4 = reinterpret_cast<const float4*>(x);
    float4* cat4 = reinterpret_cast<float4*>(s_cat);
#pragma unroll
    for (int k = 0; k < 4; ++k) {
        int i = tid + k * 256;            // 0..1023
        int c = i >> 5, r = i & 31;
        cat4[c * 32 + r] =
            x4[((b * Cc + c) * Tt + t0) * (Vv / 4) + (v0 >> 2) + r];
    }
    // comb rows 32..63 (bf16x4 via uint2, convert to f32)
    const uint2* m2 = reinterpret_cast<const uint2*>(g_comb);
#pragma unroll
    for (int k = 0; k < 4; ++k) {
        int i = tid + k * 256;            // 0..1023
        int c = i >> 5, q = i & 31;
        uint2 u = __ldg(&m2[((b * Cc + c) * Tt + t0) * (Vv / 4) + (v0 >> 2) + q]);
        float2 lo = __bfloat1622float2(*reinterpret_cast<__nv_bfloat162*>(&u.x));
        float2 hi = __bfloat1622float2(*reinterpret_cast<__nv_bfloat162*>(&u.y));
        cat4[(32 + c) * 32 + q] = make_float4(lo.x, lo.y, hi.x, hi.y);
    }
    // transposed weights
#pragma unroll
    for (int k = 0; k < 8; ++k) {
        int i = tid + k * 256;            // 0..2047
        int o = i >> 6, c = i & 63;
        s_w[c * 32 + o] = fw[i];
    }
    if (tid < 128) s_cv[tid] = g_cv[(size_t)(b * Tt + t0) * Vv + v0 + tid];
    __syncthreads();

    int og = tid >> 5;                    // warp id: o = og*4..+3
    int pg = tid & 31;                    // lane:    p = pg*4..+3
    int p0 = pg << 2;

    float acc[16];
#pragma unroll
    for (int i = 0; i < 16; ++i) acc[i] = 0.f;

#pragma unroll 16
    for (int c = 0; c < 64; ++c) {
        float4 w  = *reinterpret_cast<const float4*>(&s_w[c * 32 + (og << 2)]);
        float4 xv = *reinterpret_cast<const float4*>(&s_cat[c * 128 + p0]);
        acc[0]  += w.x * xv.x;  acc[1]  += w.x * xv.y;
        acc[2]  += w.x * xv.z;  acc[3]  += w.x * xv.w;
        acc[4]  += w.y * xv.x;  acc[5]  += w.y * xv.y;
        acc[6]  += w.y * xv.z;  acc[7]  += w.y * xv.w;
        acc[8]  += w.z * xv.x;  acc[9]  += w.z * xv.y;
        acc[10] += w.z * xv.z;  acc[11] += w.z * xv.w;
        acc[12] += w.w * xv.x;  acc[13] += w.w * xv.y;
        acc[14] += w.w * xv.z;  acc[15] += w.w * xv.w;
    }

    // epilogue: (gemm + bias + residual) * (1+cv) + impact
    float m0 = 1.f + s_cv[p0 + 0];
    float m1 = 1.f + s_cv[p0 + 1];
    float m2f = 1.f + s_cv[p0 + 2];
    float m3 = 1.f + s_cv[p0 + 3];
    float imp = __ldg(g_imp + b * Tt + t0);

#pragma unroll
    for (int oo = 0; oo < 4; ++oo) {
        int o = (og << 2) + oo;
        float fbv = __ldg(fb + o);
        float4 xres = *reinterpret_cast<const float4*>(&s_cat[o * 128 + p0]);
        float4 r;
        r.x = (acc[oo * 4 + 0] + fbv + xres.x) * m0  + imp;
        r.y = (acc[oo * 4 + 1] + fbv + xres.y) * m1  + imp;
        r.z = (acc[oo * 4 + 2] + fbv + xres.z) * m2f + imp;
        r.w = (acc[oo * 4 + 3] + fbv + xres.w) * m3  + imp;
        size_t oi = ((size_t)(b * Cc + o) * Tt + t0) * Vv + v0 + p0;
        *reinterpret_cast<float4*>(out + oi) = r;
    }
}

// ---------------------------------------------------------------------------
extern "C" void kernel_launch(void* const* d_in, const int* in_sizes, int n_in,
                              void* d_out, int out_size) {
    const float* flow   = (const float*)d_in[0];
    const float* events = (const float*)d_in[1];
    const float* x      = (const float*)d_in[2];
    const float* ef     = (const float*)d_in[3];
    const float* w1     = (const float*)d_in[4];
    const float* b1     = (const float*)d_in[5];
    const float* w2     = (const float*)d_in[6];
    const float* b2     = (const float*)d_in[7];
    const float* fw     = (const float*)d_in[8];
    const float* fb     = (const float*)d_in[9];
    float* out = (float*)d_out;

    const int smem_k1 = 64 * 128 * sizeof(float2);   // 64 KB
    cudaFuncSetAttribute(k1f, cudaFuncAttributeMaxDynamicSharedMemorySize,
                         smem_k1);

    kA<<<65, 256>>>(flow, events, ef, w1, b1, w2, b2);
    k1f<<<dim3(256, 2), 128, smem_k1>>>(x);
    k2s<<<dim3(Vv / 128, Tt, Bc), 256>>>(x, fw, fb, out);
}